// round 15
// baseline (speedup 1.0000x reference)
#include <cuda_runtime.h>
#include <cuda_bf16.h>
#include <math.h>
#include <stdint.h>

// Problem constants
#define N_TOKENS   32768
#define HIDDEN     2048
#define N_EXPERTS  256
#define N_GROUP    8
#define TOPK_GROUP 4
#define TOP_K      8
#define ROUTED_SCALING 2.5f

// GEMM config: tile 128 tokens x 128 experts, BK=8, 128 threads/CTA,
// per-thread 16 rows x 8 cols (4 fma2 col-pairs), 2 CTAs/SM.
#define BM 128
#define BN 128
#define BK 8
#define NTILES (HIDDEN / BK)     // 256
#define FLUSH_PERIOD 40          // kc=320 / BK
#define TOT_ST 132               // padded tot row stride (floats)

// dynamic smem layout (floats)
#define OFF_AS0 0
#define OFF_AS1 (BK * BM)
#define OFF_BS0 (2 * BK * BM)
#define OFF_BS1 (2 * BK * BM + BK * BN)
#define OFF_TOT (2 * BK * BM + 2 * BK * BN)
#define SMEM_FLOATS (OFF_TOT + BM * TOT_ST)
#define SMEM_BYTES  (SMEM_FLOATS * 4)   // 83,968 B

typedef unsigned long long u64;

// ---------------------------------------------------------------------------
// Packed f32x2 helpers — each lane IEEE rn, bit-identical to scalar chains.
// ---------------------------------------------------------------------------
__device__ __forceinline__ u64 pack2(float lo, float hi) {
    u64 r;
    asm("mov.b64 %0, {%1, %2};" : "=l"(r) : "f"(lo), "f"(hi));
    return r;
}
__device__ __forceinline__ void unpack2(u64 v, float& lo, float& hi) {
    asm("mov.b64 {%0, %1}, %2;" : "=f"(lo), "=f"(hi) : "l"(v));
}
__device__ __forceinline__ void fma2(u64& d, u64 a, u64 b) {
    asm("fma.rn.f32x2 %0, %1, %2, %0;" : "+l"(d) : "l"(a), "l"(b));
}
__device__ __forceinline__ void add2(u64& d, u64 a) {
    asm("add.rn.f32x2 %0, %0, %1;" : "+l"(d) : "l"(a));
}

// ---------------------------------------------------------------------------
// XLA CPU GenerateVF32Exp (Cephes) — bit-pinned reference sigmoid.
// ---------------------------------------------------------------------------
__device__ __forceinline__ float xla_expf(float v) {
    float x = fminf(fmaxf(v, -88.3762626647949f), 88.3762626647950f);
    float fx = floorf(fmaf(x, 1.44269504088896341f, 0.5f));
    float tmp = __fmul_rn(fx, 0.693359375f);
    float z2  = __fmul_rn(fx, -2.12194440e-4f);
    x = __fsub_rn(x, tmp);
    x = __fsub_rn(x, z2);
    float zz = __fmul_rn(x, x);
    float y = 1.9875691500E-4f;
    y = fmaf(y, x, 1.3981999507E-3f);
    y = fmaf(y, x, 8.3334519073E-3f);
    y = fmaf(y, x, 4.1665795894E-2f);
    y = fmaf(y, x, 1.6666665459E-1f);
    y = fmaf(y, x, 5.0000001201E-1f);
    y = fmaf(y, zz, x);
    y = __fadd_rn(y, 1.0f);
    int n = (int)fx;
    float p2n = __int_as_float((n + 127) << 23);
    return __fmul_rn(y, p2n);
}
__device__ __forceinline__ float ref_sigmoid(float L) {
    return __fdiv_rn(1.0f, __fadd_rn(1.0f, xla_expf(-L)));
}

// ---------------------------------------------------------------------------
// GEMM: C[M,E] = A[M,K] * B[E,K]^T, fp32, FFMA2 (2 cols per 64-bit acc).
// Bit-exact Eigen gebp emulation: per element one serial fma chain within
// kc=320 panels (flush to smem tot every 40 tiles), panels joined by fadd.
// Grid: 512 CTAs = 256 token-tiles x 2 expert-halves; 2 CTAs/SM.
// ---------------------------------------------------------------------------
__global__ __launch_bounds__(128, 2)
void gate_gemm_kernel(const float* __restrict__ A,
                      const float* __restrict__ B,
                      float* __restrict__ C)
{
    extern __shared__ float sm[];
    float* tot = sm + OFF_TOT;

    const int tid = threadIdx.x;
    const int tx  = tid & 15;          // 16 col groups x 8 cols (strided)
    const int ty  = tid >> 4;          // 8 row groups x 16 rows
    const int rowBase = (blockIdx.x >> 1) * BM;
    const int colBase = (blockIdx.x & 1) * BN;

    // loaders: thread tid handles A row tid and B row tid (2 float4 each)
    const float* Aptr = A + (size_t)(rowBase + tid) * HIDDEN;
    const float* Bptr = B + (size_t)(colBase + tid) * HIDDEN;

    u64 cur[16][4];
#pragma unroll
    for (int i = 0; i < 16; i++)
#pragma unroll
        for (int p = 0; p < 4; p++) cur[i][p] = 0ull;

    // prologue: stage tile 0 into buffer 0
    {
        float4 pa0 = *(const float4*)(Aptr);
        float4 pa1 = *(const float4*)(Aptr + 4);
        float4 pb0 = *(const float4*)(Bptr);
        float4 pb1 = *(const float4*)(Bptr + 4);
        float* As = sm + OFF_AS0;
        float* Bs = sm + OFF_BS0;
        As[0 * BM + tid] = pa0.x; As[1 * BM + tid] = pa0.y;
        As[2 * BM + tid] = pa0.z; As[3 * BM + tid] = pa0.w;
        As[4 * BM + tid] = pa1.x; As[5 * BM + tid] = pa1.y;
        As[6 * BM + tid] = pa1.z; As[7 * BM + tid] = pa1.w;
        Bs[0 * BN + tid] = pb0.x; Bs[1 * BN + tid] = pb0.y;
        Bs[2 * BN + tid] = pb0.z; Bs[3 * BN + tid] = pb0.w;
        Bs[4 * BN + tid] = pb1.x; Bs[5 * BN + tid] = pb1.y;
        Bs[6 * BN + tid] = pb1.z; Bs[7 * BN + tid] = pb1.w;
    }
    __syncthreads();

    for (int t = 0; t < NTILES; ++t) {
        const int buf = t & 1;

        // prefetch next tile into registers
        float4 na0, na1, nb0, nb1;
        if (t + 1 < NTILES) {
            const int k = (t + 1) * BK;
            na0 = *(const float4*)(Aptr + k);
            na1 = *(const float4*)(Aptr + k + 4);
            nb0 = *(const float4*)(Bptr + k);
            nb1 = *(const float4*)(Bptr + k + 4);
        }

        const float* As = sm + (buf ? OFF_AS1 : OFF_AS0);
        const float* Bs = sm + (buf ? OFF_BS1 : OFF_BS0);

#pragma unroll
        for (int kk = 0; kk < BK; kk++) {
            float4 ra0 = *(const float4*)&As[kk * BM + ty * 16];
            float4 ra1 = *(const float4*)&As[kk * BM + ty * 16 + 4];
            float4 ra2 = *(const float4*)&As[kk * BM + ty * 16 + 8];
            float4 ra3 = *(const float4*)&As[kk * BM + ty * 16 + 12];
            float4 rb0 = *(const float4*)&Bs[kk * BN +  0 + tx * 4];
            float4 rb1 = *(const float4*)&Bs[kk * BN + 64 + tx * 4];

            u64 b2[4];
            b2[0] = pack2(rb0.x, rb0.y); b2[1] = pack2(rb0.z, rb0.w);
            b2[2] = pack2(rb1.x, rb1.y); b2[3] = pack2(rb1.z, rb1.w);

            float ra[16];
            ra[0]=ra0.x;  ra[1]=ra0.y;  ra[2]=ra0.z;  ra[3]=ra0.w;
            ra[4]=ra1.x;  ra[5]=ra1.y;  ra[6]=ra1.z;  ra[7]=ra1.w;
            ra[8]=ra2.x;  ra[9]=ra2.y;  ra[10]=ra2.z; ra[11]=ra2.w;
            ra[12]=ra3.x; ra[13]=ra3.y; ra[14]=ra3.z; ra[15]=ra3.w;
#pragma unroll
            for (int i = 0; i < 16; i++) {
                u64 a2 = pack2(ra[i], ra[i]);
#pragma unroll
                for (int p = 0; p < 4; p++)
                    fma2(cur[i][p], a2, b2[p]);
            }
        }

        // kc=320 panel flush: after tiles 39, 79, ..., 239
        if ((t % FLUSH_PERIOD) == (FLUSH_PERIOD - 1) && t < 240) {
            const bool first = (t < FLUSH_PERIOD);
#pragma unroll
            for (int i = 0; i < 16; i++) {
                const int row = ty * 16 + i;
#pragma unroll
                for (int p = 0; p < 4; p++) {
                    const int g = p >> 1;
                    u64* tp = (u64*)&tot[row * TOT_ST + g * 64 + tx * 4 + (p & 1) * 2];
                    if (first) {
                        *tp = cur[i][p];
                    } else {
                        u64 v = *tp;
                        add2(v, cur[i][p]);
                        *tp = v;
                    }
                    cur[i][p] = 0ull;
                }
            }
        }

        // stage next tile
        if (t + 1 < NTILES) {
            float* Asn = sm + (buf ? OFF_AS0 : OFF_AS1);
            float* Bsn = sm + (buf ? OFF_BS0 : OFF_BS1);
            Asn[0 * BM + tid] = na0.x; Asn[1 * BM + tid] = na0.y;
            Asn[2 * BM + tid] = na0.z; Asn[3 * BM + tid] = na0.w;
            Asn[4 * BM + tid] = na1.x; Asn[5 * BM + tid] = na1.y;
            Asn[6 * BM + tid] = na1.z; Asn[7 * BM + tid] = na1.w;
            Bsn[0 * BN + tid] = nb0.x; Bsn[1 * BN + tid] = nb0.y;
            Bsn[2 * BN + tid] = nb0.z; Bsn[3 * BN + tid] = nb0.w;
            Bsn[4 * BN + tid] = nb1.x; Bsn[5 * BN + tid] = nb1.y;
            Bsn[6 * BN + tid] = nb1.z; Bsn[7 * BN + tid] = nb1.w;
            __syncthreads();
        }
    }

    // final: logits = tot + cur (tail panel, k 1920-2047), write C
#pragma unroll
    for (int i = 0; i < 16; i++) {
        const int row = ty * 16 + i;
#pragma unroll
        for (int g = 0; g < 2; g++) {
            u64 t0 = *(u64*)&tot[row * TOT_ST + g * 64 + tx * 4];
            u64 t1 = *(u64*)&tot[row * TOT_ST + g * 64 + tx * 4 + 2];
            add2(t0, cur[i][2 * g]);
            add2(t1, cur[i][2 * g + 1]);
            float c0, c1, c2, c3;
            unpack2(t0, c0, c1);
            unpack2(t1, c2, c3);
            *(float4*)&C[(size_t)(rowBase + row) * N_EXPERTS + colBase + g * 64 + tx * 4] =
                make_float4(c0, c1, c2, c3);
        }
    }
}

// ---------------------------------------------------------------------------
// Routing (bit-pinned, validated R7/R12). One block (256 threads) per token.
// ---------------------------------------------------------------------------
__global__ __launch_bounds__(256)
void routing_kernel(const float* __restrict__ logits,
                    const float* __restrict__ bias,
                    float* __restrict__ out_idx,
                    float* __restrict__ out_w)
{
    const int token = blockIdx.x;
    const int tid   = threadIdx.x;
    const int lane  = tid & 31;
    const int warp  = tid >> 5;

    __shared__ float sraw[N_EXPERTS];
    __shared__ float sc[N_EXPERTS];
    __shared__ float gscore[N_GROUP];
    __shared__ int   gmask[N_GROUP];
    __shared__ int   selidx[TOP_K];
    __shared__ float selsc[TOP_K];

    const float L = logits[(size_t)token * N_EXPERTS + tid];
    const float s = ref_sigmoid(L);
    const float r = __fadd_rn(s, bias[tid]);
    sraw[tid] = s;

    // group top-2 (warp = group); group score = a + b, a >= b
    float a = r, b = -INFINITY;
#pragma unroll
    for (int off = 16; off; off >>= 1) {
        float oa = __shfl_xor_sync(0xffffffffu, a, off);
        float ob = __shfl_xor_sync(0xffffffffu, b, off);
        if (oa > a) { b = fmaxf(a, ob); a = oa; }
        else        { b = fmaxf(b, oa); }
    }
    if (lane == 0) gscore[warp] = __fadd_rn(a, b);
    __syncthreads();

    // top-4 groups, tie -> lower index
    if (tid == 0) {
        float g[N_GROUP];
#pragma unroll
        for (int i = 0; i < N_GROUP; i++) g[i] = gscore[i];
        int chosen = 0;
#pragma unroll
        for (int sel = 0; sel < TOPK_GROUP; sel++) {
            float best = -INFINITY; int bi = 0;
            for (int i = 0; i < N_GROUP; i++)
                if (!((chosen >> i) & 1) && g[i] > best) { best = g[i]; bi = i; }
            chosen |= (1 << bi);
        }
#pragma unroll
        for (int i = 0; i < N_GROUP; i++) gmask[i] = (chosen >> i) & 1;
    }
    __syncthreads();

    sc[tid] = gmask[warp] ? r : -INFINITY;
    __syncthreads();

    // top-8 experts (warp 0), stable tie-break
    if (warp == 0) {
        float v[8];
#pragma unroll
        for (int j = 0; j < 8; j++) v[j] = sc[j * 32 + lane];

#pragma unroll
        for (int it = 0; it < TOP_K; it++) {
            float bv = -INFINITY; int bj = 0;
#pragma unroll
            for (int j = 0; j < 8; j++)
                if (v[j] > bv) { bv = v[j]; bj = j; }   // tie -> lower j
            float mv = bv;
            int   mi = bj * 32 + lane;
#pragma unroll
            for (int off = 16; off; off >>= 1) {
                float ov = __shfl_xor_sync(0xffffffffu, mv, off);
                int   oi = __shfl_xor_sync(0xffffffffu, mi, off);
                if (ov > mv || (ov == mv && oi < mi)) { mv = ov; mi = oi; }
            }
#pragma unroll
            for (int j = 0; j < 8; j++)
                if (mi == j * 32 + lane) v[j] = -INFINITY;
            if (lane == it) selidx[it] = mi;
        }
        __syncwarp();

        if (lane < TOP_K) selsc[lane] = sraw[selidx[lane]];
        __syncwarp();

        if (lane < TOP_K) {
            float sum = selsc[0];
#pragma unroll
            for (int j = 1; j < TOP_K; j++) sum = __fadd_rn(sum, selsc[j]);
            const float w = __fmul_rn(
                __fdiv_rn(selsc[lane], __fadd_rn(sum, 1e-20f)), ROUTED_SCALING);
            out_idx[(size_t)token * TOP_K + lane] = (float)selidx[lane];
            out_w  [(size_t)token * TOP_K + lane] = w;
        }
    }
}

// ---------------------------------------------------------------------------
extern "C" void kernel_launch(void* const* d_in, const int* in_sizes, int n_in,
                              void* d_out, int out_size)
{
    const float* hs   = (const float*)d_in[0];
    const float* w    = (const float*)d_in[1];
    const float* bias = (const float*)d_in[2];

    float* out = (float*)d_out;
    float* out_idx    = out;
    float* out_w      = out + (size_t)N_TOKENS * TOP_K;
    float* out_logits = out + (size_t)N_TOKENS * TOP_K * 2;

    cudaFuncSetAttribute(gate_gemm_kernel,
                         cudaFuncAttributeMaxDynamicSharedMemorySize, SMEM_BYTES);

    gate_gemm_kernel<<<(N_TOKENS / BM) * (N_EXPERTS / BN), 128, SMEM_BYTES>>>(
        hs, w, out_logits);
    routing_kernel<<<N_TOKENS, 256>>>(out_logits, bias, out_idx, out_w);
}

// round 17
// speedup vs baseline: 1.6473x; 1.6473x over previous
#include <cuda_runtime.h>
#include <cuda_bf16.h>
#include <math.h>
#include <stdint.h>

// Problem constants
#define N_TOKENS   32768
#define HIDDEN     2048
#define N_EXPERTS  256
#define N_GROUP    8
#define TOPK_GROUP 4
#define TOP_K      8
#define ROUTED_SCALING 2.5f

// GEMM config (R12, validated 719us): BM=128, BN=256, BK=8, 256 threads,
// per-thread 8 rows x 16 cols (8 fma2 col-pairs), 1 CTA/SM.
#define BM 128
#define BN 256
#define BK 8
#define NTILES (HIDDEN / BK)     // 256
#define FLUSH_PERIOD 40          // kc=320 / BK
#define TOT_ST 260               // padded tot row stride (floats)

// dynamic smem layout (floats)
#define OFF_AS0 0
#define OFF_AS1 (BK * BM)
#define OFF_BS0 (2 * BK * BM)
#define OFF_BS1 (2 * BK * BM + BK * BN)
#define OFF_TOT (2 * BK * BM + 2 * BK * BN)
#define SMEM_FLOATS (OFF_TOT + BM * TOT_ST)
#define SMEM_BYTES  (SMEM_FLOATS * 4)   // 157,696 B

typedef unsigned long long u64;

// ---------------------------------------------------------------------------
// Packed f32x2 helpers — each lane IEEE rn, bit-identical to scalar chains.
// ---------------------------------------------------------------------------
__device__ __forceinline__ u64 pack2(float lo, float hi) {
    u64 r;
    asm("mov.b64 %0, {%1, %2};" : "=l"(r) : "f"(lo), "f"(hi));
    return r;
}
__device__ __forceinline__ void unpack2(u64 v, float& lo, float& hi) {
    asm("mov.b64 {%0, %1}, %2;" : "=f"(lo), "=f"(hi) : "l"(v));
}
__device__ __forceinline__ void fma2(u64& d, u64 a, u64 b) {
    asm("fma.rn.f32x2 %0, %1, %2, %0;" : "+l"(d) : "l"(a), "l"(b));
}
__device__ __forceinline__ void add2(u64& d, u64 a) {
    asm("add.rn.f32x2 %0, %0, %1;" : "+l"(d) : "l"(a));
}

// ---------------------------------------------------------------------------
// XLA CPU GenerateVF32Exp (Cephes) — bit-pinned reference sigmoid.
// ---------------------------------------------------------------------------
__device__ __forceinline__ float xla_expf(float v) {
    float x = fminf(fmaxf(v, -88.3762626647949f), 88.3762626647950f);
    float fx = floorf(fmaf(x, 1.44269504088896341f, 0.5f));
    float tmp = __fmul_rn(fx, 0.693359375f);
    float z2  = __fmul_rn(fx, -2.12194440e-4f);
    x = __fsub_rn(x, tmp);
    x = __fsub_rn(x, z2);
    float zz = __fmul_rn(x, x);
    float y = 1.9875691500E-4f;
    y = fmaf(y, x, 1.3981999507E-3f);
    y = fmaf(y, x, 8.3334519073E-3f);
    y = fmaf(y, x, 4.1665795894E-2f);
    y = fmaf(y, x, 1.6666665459E-1f);
    y = fmaf(y, x, 5.0000001201E-1f);
    y = fmaf(y, zz, x);
    y = __fadd_rn(y, 1.0f);
    int n = (int)fx;
    float p2n = __int_as_float((n + 127) << 23);
    return __fmul_rn(y, p2n);
}
__device__ __forceinline__ float ref_sigmoid(float L) {
    return __fdiv_rn(1.0f, __fadd_rn(1.0f, xla_expf(-L)));
}

// ---------------------------------------------------------------------------
// GEMM (R12 verbatim): C[M,E] = A[M,K] * B[E,K]^T, fp32, FFMA2.
// Bit-exact Eigen gebp emulation: per element one serial fma chain within
// kc=320 panels (flush to smem tot every 40 tiles), panels joined by fadd.
// ---------------------------------------------------------------------------
__global__ __launch_bounds__(256, 1)
void gate_gemm_kernel(const float* __restrict__ A,
                      const float* __restrict__ B,
                      float* __restrict__ C)
{
    extern __shared__ float sm[];
    float* tot = sm + OFF_TOT;

    const int tid = threadIdx.x;
    const int tx  = tid & 15;
    const int ty  = tid >> 4;
    const int rowBase = blockIdx.x * BM;

    const int ar = tid & 127;
    const int ac = (tid >> 7) * 4;
    const int br = tid;

    const float* Aptr = A + (size_t)(rowBase + ar) * HIDDEN + ac;
    const float* Bptr = B + (size_t)br * HIDDEN;

    u64 cur[8][8];
#pragma unroll
    for (int i = 0; i < 8; i++)
#pragma unroll
        for (int p = 0; p < 8; p++) cur[i][p] = 0ull;

    {
        float4 pa  = *(const float4*)(Aptr);
        float4 pb0 = *(const float4*)(Bptr);
        float4 pb1 = *(const float4*)(Bptr + 4);
        float* As = sm + OFF_AS0;
        float* Bs = sm + OFF_BS0;
        As[(ac + 0) * BM + ar] = pa.x; As[(ac + 1) * BM + ar] = pa.y;
        As[(ac + 2) * BM + ar] = pa.z; As[(ac + 3) * BM + ar] = pa.w;
        Bs[0 * BN + br] = pb0.x; Bs[1 * BN + br] = pb0.y;
        Bs[2 * BN + br] = pb0.z; Bs[3 * BN + br] = pb0.w;
        Bs[4 * BN + br] = pb1.x; Bs[5 * BN + br] = pb1.y;
        Bs[6 * BN + br] = pb1.z; Bs[7 * BN + br] = pb1.w;
    }
    __syncthreads();

    for (int t = 0; t < NTILES; ++t) {
        const int buf = t & 1;

        float4 na, nb0, nb1;
        if (t + 1 < NTILES) {
            const int k = (t + 1) * BK;
            na  = *(const float4*)(Aptr + k);
            nb0 = *(const float4*)(Bptr + k);
            nb1 = *(const float4*)(Bptr + k + 4);
        }

        const float* As = sm + (buf ? OFF_AS1 : OFF_AS0);
        const float* Bs = sm + (buf ? OFF_BS1 : OFF_BS0);

#pragma unroll
        for (int kk = 0; kk < BK; kk++) {
            float4 ra0 = *(const float4*)&As[kk * BM + ty * 8];
            float4 ra1 = *(const float4*)&As[kk * BM + ty * 8 + 4];
            float4 rb0 = *(const float4*)&Bs[kk * BN +   0 + tx * 4];
            float4 rb1 = *(const float4*)&Bs[kk * BN +  64 + tx * 4];
            float4 rb2 = *(const float4*)&Bs[kk * BN + 128 + tx * 4];
            float4 rb3 = *(const float4*)&Bs[kk * BN + 192 + tx * 4];

            u64 b2[8];
            b2[0] = pack2(rb0.x, rb0.y); b2[1] = pack2(rb0.z, rb0.w);
            b2[2] = pack2(rb1.x, rb1.y); b2[3] = pack2(rb1.z, rb1.w);
            b2[4] = pack2(rb2.x, rb2.y); b2[5] = pack2(rb2.z, rb2.w);
            b2[6] = pack2(rb3.x, rb3.y); b2[7] = pack2(rb3.z, rb3.w);

            float ra[8];
            ra[0]=ra0.x; ra[1]=ra0.y; ra[2]=ra0.z; ra[3]=ra0.w;
            ra[4]=ra1.x; ra[5]=ra1.y; ra[6]=ra1.z; ra[7]=ra1.w;
#pragma unroll
            for (int i = 0; i < 8; i++) {
                u64 a2 = pack2(ra[i], ra[i]);
#pragma unroll
                for (int p = 0; p < 8; p++)
                    fma2(cur[i][p], a2, b2[p]);
            }
        }

        if ((t % FLUSH_PERIOD) == (FLUSH_PERIOD - 1) && t < 240) {
            const bool first = (t < FLUSH_PERIOD);
#pragma unroll
            for (int i = 0; i < 8; i++) {
                const int row = ty * 8 + i;
#pragma unroll
                for (int p = 0; p < 8; p++) {
                    const int g = p >> 1;
                    u64* tp = (u64*)&tot[row * TOT_ST + g * 64 + tx * 4 + (p & 1) * 2];
                    if (first) {
                        *tp = cur[i][p];
                    } else {
                        u64 v = *tp;
                        add2(v, cur[i][p]);
                        *tp = v;
                    }
                    cur[i][p] = 0ull;
                }
            }
        }

        if (t + 1 < NTILES) {
            float* Asn = sm + (buf ? OFF_AS0 : OFF_AS1);
            float* Bsn = sm + (buf ? OFF_BS0 : OFF_BS1);
            Asn[(ac + 0) * BM + ar] = na.x; Asn[(ac + 1) * BM + ar] = na.y;
            Asn[(ac + 2) * BM + ar] = na.z; Asn[(ac + 3) * BM + ar] = na.w;
            Bsn[0 * BN + br] = nb0.x; Bsn[1 * BN + br] = nb0.y;
            Bsn[2 * BN + br] = nb0.z; Bsn[3 * BN + br] = nb0.w;
            Bsn[4 * BN + br] = nb1.x; Bsn[5 * BN + br] = nb1.y;
            Bsn[6 * BN + br] = nb1.z; Bsn[7 * BN + br] = nb1.w;
            __syncthreads();
        }
    }

#pragma unroll
    for (int i = 0; i < 8; i++) {
        const int row = ty * 8 + i;
#pragma unroll
        for (int g = 0; g < 4; g++) {
            u64 t0 = *(u64*)&tot[row * TOT_ST + g * 64 + tx * 4];
            u64 t1 = *(u64*)&tot[row * TOT_ST + g * 64 + tx * 4 + 2];
            add2(t0, cur[i][2 * g]);
            add2(t1, cur[i][2 * g + 1]);
            float c0, c1, c2, c3;
            unpack2(t0, c0, c1);
            unpack2(t1, c2, c3);
            *(float4*)&C[(size_t)(rowBase + row) * N_EXPERTS + g * 64 + tx * 4] =
                make_float4(c0, c1, c2, c3);
        }
    }
}

// ---------------------------------------------------------------------------
// Routing: ONE WARP PER TOKEN (warp-local algorithm bit-validated in R13).
// Grid 4096 x 256 threads; warp w -> token blockIdx*8 + w.
// Expert j*32+lane lives in register slot j; group j == register j.
// ---------------------------------------------------------------------------
__global__ __launch_bounds__(256)
void routing_kernel(const float* __restrict__ logits,
                    const float* __restrict__ bias,
                    float* __restrict__ out_idx,
                    float* __restrict__ out_w)
{
    const int tid  = threadIdx.x;
    const int lane = tid & 31;
    const int warp = tid >> 5;
    const int token = blockIdx.x * 8 + warp;

    // bias per lane slot
    float bias8[8];
#pragma unroll
    for (int j = 0; j < 8; j++) bias8[j] = bias[j * 32 + lane];

    // load logits, sigmoid, biased scores
    const float* lrow = logits + (size_t)token * N_EXPERTS;
    float s8[8], r8[8];
#pragma unroll
    for (int j = 0; j < 8; j++) {
        const float L = lrow[j * 32 + lane];
        s8[j] = ref_sigmoid(L);
        r8[j] = __fadd_rn(s8[j], bias8[j]);
    }

    // group scores: top-2 per group via max / exclude-one / max (R13-validated).
    float g8[8];
#pragma unroll
    for (int j = 0; j < 8; j++) {
        float m1 = r8[j];
#pragma unroll
        for (int off = 16; off; off >>= 1)
            m1 = fmaxf(m1, __shfl_xor_sync(0xffffffffu, m1, off));
        unsigned eq = __ballot_sync(0xffffffffu, r8[j] == m1);
        int leader = __ffs(eq) - 1;
        float v2 = (lane == leader) ? -INFINITY : r8[j];
#pragma unroll
        for (int off = 16; off; off >>= 1)
            v2 = fmaxf(v2, __shfl_xor_sync(0xffffffffu, v2, off));
        g8[j] = __fadd_rn(m1, v2);
    }

    // top-4 groups (all lanes redundantly), tie -> lower index
    int chosen = 0;
#pragma unroll
    for (int sel = 0; sel < TOPK_GROUP; sel++) {
        float best = -INFINITY; int bi = 0;
#pragma unroll
        for (int i = 0; i < N_GROUP; i++)
            if (!((chosen >> i) & 1) && g8[i] > best) { best = g8[i]; bi = i; }
        chosen |= (1 << bi);
    }

    float v[8];
#pragma unroll
    for (int j = 0; j < 8; j++)
        v[j] = ((chosen >> j) & 1) ? r8[j] : -INFINITY;

    // top-8 iterative argmax, stable tie-break (R13-validated)
    int   my_idx = 0;
    float my_s   = 0.0f;
    float sels[TOP_K];
#pragma unroll
    for (int it = 0; it < TOP_K; it++) {
        float bv = -INFINITY; int bj = 0;
#pragma unroll
        for (int j = 0; j < 8; j++)
            if (v[j] > bv) { bv = v[j]; bj = j; }   // tie -> lower j
        float mv = bv;
        int   mi = bj * 32 + lane;
#pragma unroll
        for (int off = 16; off; off >>= 1) {
            float ov = __shfl_xor_sync(0xffffffffu, mv, off);
            int   oi = __shfl_xor_sync(0xffffffffu, mi, off);
            if (ov > mv || (ov == mv && oi < mi)) { mv = ov; mi = oi; }
        }
        float sval = 0.0f;
#pragma unroll
        for (int j = 0; j < 8; j++)
            if (mi == j * 32 + lane) { v[j] = -INFINITY; sval = s8[j]; }
        float sw = __shfl_sync(0xffffffffu, sval, mi & 31);
        sels[it] = sw;
        if (lane == it) { my_idx = mi; my_s = sw; }
    }

    // weights: serial sum in selection (descending) order — R7 semantics
    float sum = sels[0];
#pragma unroll
    for (int j = 1; j < TOP_K; j++) sum = __fadd_rn(sum, sels[j]);

    if (lane < TOP_K) {
        const float w = __fmul_rn(
            __fdiv_rn(my_s, __fadd_rn(sum, 1e-20f)), ROUTED_SCALING);
        out_idx[(size_t)token * TOP_K + lane] = (float)my_idx;
        out_w  [(size_t)token * TOP_K + lane] = w;
    }
}

// ---------------------------------------------------------------------------
extern "C" void kernel_launch(void* const* d_in, const int* in_sizes, int n_in,
                              void* d_out, int out_size)
{
    const float* hs   = (const float*)d_in[0];
    const float* w    = (const float*)d_in[1];
    const float* bias = (const float*)d_in[2];

    float* out = (float*)d_out;
    float* out_idx    = out;
    float* out_w      = out + (size_t)N_TOKENS * TOP_K;
    float* out_logits = out + (size_t)N_TOKENS * TOP_K * 2;

    cudaFuncSetAttribute(gate_gemm_kernel,
                         cudaFuncAttributeMaxDynamicSharedMemorySize, SMEM_BYTES);

    gate_gemm_kernel<<<N_TOKENS / BM, 256, SMEM_BYTES>>>(hs, w, out_logits);
    routing_kernel<<<N_TOKENS / 8, 256>>>(out_logits, bias, out_idx, out_w);
}